// round 1
// baseline (speedup 1.0000x reference)
#include <cuda_runtime.h>
#include <math.h>

typedef long long LL;

#define BATCH   16
#define SEQ     197
#define NPATCH  196
#define DIM     768
#define NH      12
#define HDK     9216   /* NH*DIM */
#define MLP     3072
#define ROWS    (BATCH*SEQ)     /* 3152 */
#define PROWS   (BATCH*NPATCH)  /* 3136 */
#define NLAYER  4
#define NC      4

// ---------------- scratch (device globals; allocation-free) ----------------
__device__ float g_Xp [PROWS*DIM];        // im2col
__device__ float g_PO [PROWS*DIM];        // patch GEMM out
__device__ float g_WpT[DIM*DIM];          // transposed patch weight
__device__ float g_H  [ROWS*DIM];         // residual stream
__device__ float g_Xn [ROWS*DIM];         // LN output
__device__ float g_Wf [DIM*HDK];          // folded QKV weight (reused q/k/v)
__device__ float g_Bf [HDK];              // folded QKV bias
__device__ float g_Q  [ROWS*HDK];         // Q, later reused as "cat" (av output)
__device__ float g_K  [ROWS*HDK];
__device__ float g_V  [ROWS*HDK];
__device__ float g_S  [BATCH*NH*SEQ*SEQ]; // scores / probs
__device__ float g_Hid[ROWS*MLP];         // MLP hidden

// ---------------- small kernels ----------------
__global__ void transpose_k(const float* __restrict__ in, float* __restrict__ out) {
    int idx = blockIdx.x*blockDim.x + threadIdx.x;
    if (idx >= DIM*DIM) return;
    int d = idx % DIM, f = idx / DIM;
    out[idx] = in[d*DIM + f];           // out[f][d] = Wp[d][f]
}

__global__ void im2col_k(const float* __restrict__ x, float* __restrict__ out) {
    int idx = blockIdx.x*blockDim.x + threadIdx.x;
    if (idx >= PROWS*DIM) return;
    int f   = idx % DIM;
    int row = idx / DIM;
    int b = row / NPATCH, n = row % NPATCH;
    int ph = n / 14, pw = n % 14;
    int c = f / 256, r = f % 256;
    int p = r / 16,  q = r % 16;
    out[idx] = x[(((LL)b*3 + c)*224 + ph*16 + p)*224 + pw*16 + q];
}

__global__ void assemble_k(const float* __restrict__ patch, const float* __restrict__ cls,
                           const float* __restrict__ pos, float* __restrict__ h) {
    int idx = blockIdx.x*blockDim.x + threadIdx.x;
    if (idx >= ROWS*DIM) return;
    int d = idx % DIM;
    int row = idx / DIM;
    int b = row / SEQ, s = row % SEQ;
    float v = (s == 0) ? cls[d] : patch[((LL)b*NPATCH + (s-1))*DIM + d];
    h[idx] = v + pos[s*DIM + d];
}

// fold: Wf[d][h*DIM+k] = g1[h][d] * Wq[h][d][k]
__global__ void fold_w_k(const float* __restrict__ W, const float* __restrict__ g,
                         float* __restrict__ out) {
    int idx = blockIdx.x*blockDim.x + threadIdx.x;
    if (idx >= NH*DIM*DIM) return;
    int k = idx % DIM;
    int d = (idx / DIM) % DIM;
    int h = idx / (DIM*DIM);
    out[(LL)d*HDK + h*DIM + k] = g[h*DIM + d] * W[idx];
}

// Bf[h*DIM+k] = bq[h][k] + sum_d b1[h][d] * Wq[h][d][k]
__global__ void fold_b_k(const float* __restrict__ W, const float* __restrict__ b1,
                         const float* __restrict__ bq, float* __restrict__ out) {
    int hk = blockIdx.x*blockDim.x + threadIdx.x;
    if (hk >= HDK) return;
    int h = hk / DIM, k = hk % DIM;
    float s = bq[hk];
    const float* Wh = W + (LL)h*DIM*DIM;
    for (int d = 0; d < DIM; d++) s = fmaf(b1[h*DIM + d], Wh[(LL)d*DIM + k], s);
    out[hk] = s;
}

template<bool AFF>
__global__ void ln_k(const float* __restrict__ in, const float* __restrict__ g,
                     const float* __restrict__ b, float* __restrict__ out) {
    int row = blockIdx.x;
    const float* xr = in + (LL)row*DIM;
    int t = threadIdx.x;                 // 256 threads, 3 elems each
    float v0 = xr[t], v1 = xr[t+256], v2 = xr[t+512];
    __shared__ float rs[256], rss[256];
    rs[t]  = v0 + v1 + v2;
    rss[t] = v0*v0 + v1*v1 + v2*v2;
    __syncthreads();
    for (int off = 128; off > 0; off >>= 1) {
        if (t < off) { rs[t] += rs[t+off]; rss[t] += rss[t+off]; }
        __syncthreads();
    }
    float mu   = rs[0]  * (1.f/768.f);
    float var  = rss[0] * (1.f/768.f) - mu*mu;
    float rstd = rsqrtf(var + 1e-5f);
    float* orow = out + (LL)row*DIM;
    float y0 = (v0-mu)*rstd, y1 = (v1-mu)*rstd, y2 = (v2-mu)*rstd;
    if (AFF) {
        y0 = y0*g[t]     + b[t];
        y1 = y1*g[t+256] + b[t+256];
        y2 = y2*g[t+512] + b[t+512];
    }
    orow[t] = y0; orow[t+256] = y1; orow[t+512] = y2;
}

// softmax over the QUERY axis (columns of the [q,k] matrix)
__global__ void softmax_q_k(float* __restrict__ S) {
    LL base = (LL)blockIdx.x * (SEQ*SEQ);
    int k = threadIdx.x;
    if (k >= SEQ) return;
    float mx = -1e30f;
    for (int q = 0; q < SEQ; q++) mx = fmaxf(mx, S[base + (LL)q*SEQ + k]);
    float sum = 0.f;
    for (int q = 0; q < SEQ; q++) sum += expf(S[base + (LL)q*SEQ + k] - mx);
    float inv = 1.f / sum;
    for (int q = 0; q < SEQ; q++) {
        LL i = base + (LL)q*SEQ + k;
        S[i] = expf(S[i] - mx) * inv;
    }
}

__global__ void final_head_k(const float* __restrict__ h, const float* __restrict__ g,
                             const float* __restrict__ b, const float* __restrict__ Wc,
                             const float* __restrict__ bc, float* __restrict__ out) {
    int bi = blockIdx.x;
    const float* xr = h + (LL)bi*SEQ*DIM;   // CLS row (s=0)
    int t = threadIdx.x;
    float v0 = xr[t], v1 = xr[t+256], v2 = xr[t+512];
    __shared__ float rs[256], rss[256];
    rs[t]  = v0 + v1 + v2;
    rss[t] = v0*v0 + v1*v1 + v2*v2;
    __syncthreads();
    for (int off = 128; off > 0; off >>= 1) {
        if (t < off) { rs[t] += rs[t+off]; rss[t] += rss[t+off]; }
        __syncthreads();
    }
    float mu   = rs[0]  * (1.f/768.f);
    float rstd = rsqrtf(rss[0]*(1.f/768.f) - mu*mu + 1e-5f);
    __shared__ float pa[NC][256];
    float a[NC] = {0.f, 0.f, 0.f, 0.f};
    float vv[3] = {v0, v1, v2};
    #pragma unroll
    for (int i = 0; i < 3; i++) {
        int d = t + i*256;
        float y = (vv[i]-mu)*rstd*g[d] + b[d];
        #pragma unroll
        for (int c = 0; c < NC; c++) a[c] = fmaf(y, Wc[d*NC + c], a[c]);
    }
    #pragma unroll
    for (int c = 0; c < NC; c++) pa[c][t] = a[c];
    __syncthreads();
    for (int off = 128; off > 0; off >>= 1) {
        if (t < off) {
            #pragma unroll
            for (int c = 0; c < NC; c++) pa[c][t] += pa[c][t+off];
        }
        __syncthreads();
    }
    if (t < NC) out[bi*NC + t] = pa[t][0] + bc[t];
}

// ---------------- generic tiled SGEMM ----------------
// C[m,n] = alpha * sum_k A[m,k] * (TB ? B[n,k] : B[k,n])  (+bias[n]) (+res[m,n]) (gelu)
// batched via blockIdx.z with 2-level offsets: off = (z/zdiv)*s0 + (z%zdiv)*s1
#define EPI_BIAS 1
#define EPI_RES  2
#define EPI_GELU 4

template<int BM,int BN,int BK,int TM,int TN,bool TB,int EPI>
__global__ void __launch_bounds__((BM/TM)*(BN/TN))
gemm_k(const float* __restrict__ A, int lda, LL sA0, LL sA1,
       const float* __restrict__ B, int ldb, LL sB0, LL sB1,
       float* __restrict__ C, int ldc, LL sC0, LL sC1,
       const float* __restrict__ bias,
       const float* __restrict__ res, int ldres,
       int zdiv, int M, int N, int K, float alpha)
{
    constexpr int THREADS = (BM/TM)*(BN/TN);
    const int bz = blockIdx.z;
    const int zo = bz / zdiv, zi = bz - zo*zdiv;
    A += zo*sA0 + zi*sA1;
    B += zo*sB0 + zi*sB1;
    C += zo*sC0 + zi*sC1;

    __shared__ float As[BK][BM+4];
    __shared__ float Bs[BK][BN+4];

    const int bm = blockIdx.y*BM, bn = blockIdx.x*BN;
    const int tid = threadIdx.x;
    const int ncols = BN/TN;
    const int tr = tid / ncols;
    const int tc = tid % ncols;

    float acc[TM][TN];
    #pragma unroll
    for (int i = 0; i < TM; i++)
        #pragma unroll
        for (int j = 0; j < TN; j++) acc[i][j] = 0.f;

    for (int k0 = 0; k0 < K; k0 += BK) {
        #pragma unroll
        for (int it = 0; it < (BM*BK)/THREADS; it++) {
            int i = tid + it*THREADS;
            int m = i / BK, kk = i % BK;
            int gm = bm + m, gk = k0 + kk;
            As[kk][m] = (gm < M && gk < K) ? A[(LL)gm*lda + gk] : 0.f;
        }
        if (TB) {
            #pragma unroll
            for (int it = 0; it < (BN*BK)/THREADS; it++) {
                int i = tid + it*THREADS;
                int n = i / BK, kk = i % BK;
                int gn = bn + n, gk = k0 + kk;
                Bs[kk][n] = (gn < N && gk < K) ? B[(LL)gn*ldb + gk] : 0.f;
            }
        } else {
            #pragma unroll
            for (int it = 0; it < (BK*BN)/THREADS; it++) {
                int i = tid + it*THREADS;
                int kk = i / BN, n = i % BN;
                int gk = k0 + kk, gn = bn + n;
                Bs[kk][n] = (gk < K && gn < N) ? B[(LL)gk*ldb + gn] : 0.f;
            }
        }
        __syncthreads();
        #pragma unroll
        for (int kk = 0; kk < BK; kk++) {
            float ra[TM], rb[TN];
            #pragma unroll
            for (int i = 0; i < TM; i++) ra[i] = As[kk][tr*TM + i];
            #pragma unroll
            for (int j = 0; j < TN; j++) rb[j] = Bs[kk][tc*TN + j];
            #pragma unroll
            for (int i = 0; i < TM; i++)
                #pragma unroll
                for (int j = 0; j < TN; j++)
                    acc[i][j] = fmaf(ra[i], rb[j], acc[i][j]);
        }
        __syncthreads();
    }

    #pragma unroll
    for (int i = 0; i < TM; i++) {
        int m = bm + tr*TM + i;
        if (m >= M) continue;
        #pragma unroll
        for (int j = 0; j < TN; j++) {
            int n = bn + tc*TN + j;
            if (n >= N) continue;
            float v = acc[i][j] * alpha;
            if (EPI & EPI_BIAS) v += bias[n];
            if (EPI & EPI_RES)  v += res[(LL)m*ldres + n];
            if (EPI & EPI_GELU) v = 0.5f*v*(1.f + erff(v*0.70710678118654752440f));
            C[(LL)m*ldc + n] = v;
        }
    }
}

// ---------------- orchestration ----------------
extern "C" void kernel_launch(void* const* d_in, const int* in_sizes, int n_in,
                              void* d_out, int out_size)
{
    const float* x      = (const float*)d_in[0];
    const float* Wpatch = (const float*)d_in[1];
    const float* bpatch = (const float*)d_in[2];
    const float* cls    = (const float*)d_in[3];
    const float* pos    = (const float*)d_in[4];
    const float* ln1g   = (const float*)d_in[5];
    const float* ln1b   = (const float*)d_in[6];
    const float* Wq     = (const float*)d_in[7];
    const float* bq     = (const float*)d_in[8];
    const float* Wk     = (const float*)d_in[9];
    const float* bk     = (const float*)d_in[10];
    const float* Wv     = (const float*)d_in[11];
    const float* bv     = (const float*)d_in[12];
    const float* Wo     = (const float*)d_in[13];
    const float* bo     = (const float*)d_in[14];
    const float* ln2g   = (const float*)d_in[15];
    const float* ln2b   = (const float*)d_in[16];
    const float* W1     = (const float*)d_in[17];
    const float* b1m    = (const float*)d_in[18];
    const float* W2     = (const float*)d_in[19];
    const float* b2m    = (const float*)d_in[20];
    const float* lnfg   = (const float*)d_in[21];
    const float* lnfb   = (const float*)d_in[22];
    const float* Wc     = (const float*)d_in[23];
    const float* bc     = (const float*)d_in[24];
    float* out = (float*)d_out;

    float *Xp, *PO, *WpT, *H, *Xn, *Wf, *Bf, *Q, *Kb, *V, *S, *Hid;
    { void* p;
      cudaGetSymbolAddress(&p, g_Xp);  Xp  = (float*)p;
      cudaGetSymbolAddress(&p, g_PO);  PO  = (float*)p;
      cudaGetSymbolAddress(&p, g_WpT); WpT = (float*)p;
      cudaGetSymbolAddress(&p, g_H);   H   = (float*)p;
      cudaGetSymbolAddress(&p, g_Xn);  Xn  = (float*)p;
      cudaGetSymbolAddress(&p, g_Wf);  Wf  = (float*)p;
      cudaGetSymbolAddress(&p, g_Bf);  Bf  = (float*)p;
      cudaGetSymbolAddress(&p, g_Q);   Q   = (float*)p;
      cudaGetSymbolAddress(&p, g_K);   Kb  = (float*)p;
      cudaGetSymbolAddress(&p, g_V);   V   = (float*)p;
      cudaGetSymbolAddress(&p, g_S);   S   = (float*)p;
      cudaGetSymbolAddress(&p, g_Hid); Hid = (float*)p;
    }

    const float inv_scale = 1.0f / sqrtf(768.0f);

    // ---- patch embed ----
    transpose_k<<<(DIM*DIM + 255)/256, 256>>>(Wpatch, WpT);
    im2col_k<<<(PROWS*DIM + 255)/256, 256>>>(x, Xp);
    {
        dim3 grid((DIM+127)/128, (PROWS+127)/128, 1);
        gemm_k<128,128,8,8,8,false,EPI_BIAS><<<grid,256>>>(
            Xp, DIM, 0, 0,  WpT, DIM, 0, 0,  PO, DIM, 0, 0,
            bpatch, nullptr, 0, 1, PROWS, DIM, DIM, 1.f);
    }
    assemble_k<<<(ROWS*DIM + 255)/256, 256>>>(PO, cls, pos, H);

    // ---- transformer layers ----
    for (int l = 0; l < NLAYER; l++) {
        const float* ln1g_l = ln1g + (LL)l*NH*DIM;
        const float* ln1b_l = ln1b + (LL)l*NH*DIM;
        const float* Wqkv[3] = { Wq + (LL)l*NH*DIM*DIM, Wk + (LL)l*NH*DIM*DIM, Wv + (LL)l*NH*DIM*DIM };
        const float* bqkv[3] = { bq + (LL)l*NH*DIM,     bk + (LL)l*NH*DIM,     bv + (LL)l*NH*DIM };
        float* QKV[3] = { Q, Kb, V };
        const float* Wo_l = Wo  + (LL)l*HDK*DIM;
        const float* bo_l = bo  + (LL)l*DIM;
        const float* g2_l = ln2g + (LL)l*DIM;
        const float* b2_l = ln2b + (LL)l*DIM;
        const float* W1_l = W1  + (LL)l*DIM*MLP;
        const float* b1_l = b1m + (LL)l*MLP;
        const float* W2_l = W2  + (LL)l*MLP*DIM;
        const float* bb2_l= b2m + (LL)l*DIM;

        // LN1 (no affine — folded into QKV weights)
        ln_k<false><<<ROWS, 256>>>(H, nullptr, nullptr, Xn);

        for (int m = 0; m < 3; m++) {
            fold_w_k<<<(NH*DIM*DIM + 255)/256, 256>>>(Wqkv[m], ln1g_l, Wf);
            fold_b_k<<<(HDK + 255)/256, 256>>>(Wqkv[m], ln1b_l, bqkv[m], Bf);
            dim3 grid(HDK/128, (ROWS+127)/128, 1);
            gemm_k<128,128,8,8,8,false,EPI_BIAS><<<grid,256>>>(
                Xn, DIM, 0, 0,  Wf, HDK, 0, 0,  QKV[m], HDK, 0, 0,
                Bf, nullptr, 0, 1, ROWS, HDK, DIM, 1.f);
        }

        // scores[b,h,q,k] = Q·K / sqrt(768)  (batched NT)
        {
            dim3 grid((SEQ+63)/64, (SEQ+63)/64, BATCH*NH);
            gemm_k<64,64,16,4,4,true,0><<<grid,256>>>(
                Q,  HDK, (LL)SEQ*HDK, (LL)DIM,
                Kb, HDK, (LL)SEQ*HDK, (LL)DIM,
                S,  SEQ, (LL)NH*SEQ*SEQ, (LL)SEQ*SEQ,
                nullptr, nullptr, 0, NH, SEQ, SEQ, DIM, inv_scale);
        }
        // softmax over query axis (columns)
        softmax_q_k<<<BATCH*NH, 224>>>(S);
        // av = probs @ V, written directly in "cat" layout into Q buffer
        {
            dim3 grid(DIM/64, (SEQ+63)/64, BATCH*NH);
            gemm_k<64,64,16,4,4,false,0><<<grid,256>>>(
                S, SEQ, (LL)NH*SEQ*SEQ, (LL)SEQ*SEQ,
                V, HDK, (LL)SEQ*HDK, (LL)DIM,
                Q, HDK, (LL)SEQ*HDK, (LL)DIM,
                nullptr, nullptr, 0, NH, SEQ, DIM, SEQ, 1.f);
        }
        // out proj + bias + residual -> H
        {
            dim3 grid(DIM/128, (ROWS+127)/128, 1);
            gemm_k<128,128,8,8,8,false,EPI_BIAS|EPI_RES><<<grid,256>>>(
                Q, HDK, 0, 0,  Wo_l, DIM, 0, 0,  H, DIM, 0, 0,
                bo_l, H, DIM, 1, ROWS, DIM, HDK, 1.f);
        }
        // LN2 with affine
        ln_k<true><<<ROWS, 256>>>(H, g2_l, b2_l, Xn);
        // MLP fc1 + bias + GELU(exact)
        {
            dim3 grid(MLP/128, (ROWS+127)/128, 1);
            gemm_k<128,128,8,8,8,false,EPI_BIAS|EPI_GELU><<<grid,256>>>(
                Xn, DIM, 0, 0,  W1_l, MLP, 0, 0,  Hid, MLP, 0, 0,
                b1_l, nullptr, 0, 1, ROWS, MLP, DIM, 1.f);
        }
        // MLP fc2 + bias + residual -> H
        {
            dim3 grid(DIM/128, (ROWS+127)/128, 1);
            gemm_k<128,128,8,8,8,false,EPI_BIAS|EPI_RES><<<grid,256>>>(
                Hid, MLP, 0, 0,  W2_l, DIM, 0, 0,  H, DIM, 0, 0,
                bb2_l, H, DIM, 1, ROWS, DIM, MLP, 1.f);
        }
    }

    // ---- final LN on CLS + classifier ----
    final_head_k<<<BATCH, 256>>>(H, lnfg, lnfb, Wc, bc, out);
}